// round 10
// baseline (speedup 1.0000x reference)
// LocallyConnected2d (B=16, C=32, O=32, 64x64, k=3x3, pad=1) — sm_100a.
// Block = 8 adjacent pixels, 128 threads; warp = 2 pixels; thread tile
// 4b x 8o, fp32x2 over channel pairs. Weight smem layout: row pk = 64 f,
// chunk j of o-slot og at granule (4j+og+r(pk)) mod 16,
// r(pk) = (F0(pk%9) + 4*(pk/9)) mod 8, F0 = {0,1,2,3,4,5,6,7,3}; intra-
// granule rotate 2*((pk/9)&1). Reads 1 wavefront/LDS.128; STS <=2-way.
// R10: distance-2 L2-prefetch (registerless) + distance-1 fused LDG->STS,
// split-oi compute halves; launch_bounds(128,3) -> 3 blocks/SM.

#include <cuda_runtime.h>

typedef unsigned long long u64t;

__device__ __forceinline__ u64t fma_f32x2(u64t a, u64t b, u64t c) {
    u64t d;
    asm("fma.rn.f32x2 %0, %1, %2, %3;" : "=l"(d) : "l"(a), "l"(b), "l"(c));
    return d;
}

#define WBUF_F 4608
#define XBUF_F 1080
#define XBASE_F (2 * WBUF_F)

__global__ __launch_bounds__(128, 3)
void lc2d_main(const float* __restrict__ xin,
               const float* __restrict__ wgt,
               float* __restrict__ out)
{
    __shared__ __align__(16) float sh[2 * WBUF_F + 2 * XBUF_F];  // 45.5 KB

    const int tid  = threadIdx.x;
    const int lane = tid & 31;
    const int og   = lane & 3;
    const int bg   = (lane >> 2) & 3;
    const int pix  = (tid >> 5) * 2 + (lane >> 4);   // 0..7
    const int swp  = pix & 1;

    const int oh      = blockIdx.y;
    const int ow0     = blockIdx.x << 3;
    const int pixbase = oh * 64 + ow0;

    // ---- weight staging invariants: 9 float4/thread, offsets packed 16b ----
    int wgofs[9];
    unsigned wpack[18];
#pragma unroll
    for (int s = 0; s < 9; ++s) {
        int f   = tid + s * 128;
        int run = f / 18;
        int v4  = f - run * 18;
        int o   = run >> 1;
        int cc  = run & 1;
        wgofs[s] = ((o * 32 + cc) * 4096 + pixbase) * 9 + v4 * 4;
        int idx16 = (o & 7) * 2 + cc;
        int Cb    = (idx16 & ~3) + (o >> 3);
        int pos0  = idx16 & 3;
        int stv[4];
#pragma unroll
        for (int e = 0; e < 4; ++e) {
            int pk = v4 * 4 + e;                  // 0..71
            int p  = (pk * 57) >> 9;              // == pk / 9
            int q  = pk - p * 9;
            int f0 = q - 5 * (q >> 3);            // {0..7,3}
            int rt = (f0 + 4 * p) & 7;
            stv[e] = pk * 64 + ((Cb + rt) & 15) * 4 + ((pos0 + 2 * (p & 1)) & 3);
        }
        wpack[s * 2]     = (unsigned)stv[0] | ((unsigned)stv[1] << 16);
        wpack[s * 2 + 1] = (unsigned)stv[2] | ((unsigned)stv[3] << 16);
    }

    // ---- x staging invariants: slots 0..6 all threads, slot 7 iff tid<64 ----
    int xgofs[8];
    unsigned xpack[4];
#pragma unroll
    for (int s = 0; s < 8; ++s) {
        int i  = tid + s * 128;
        int so = 0;
        xgofs[s] = -1;
        if (i < 960) {
            int col = i % 10;
            int r   = i / 10;
            int row = r % 3;
            int qb  = r / 3;
            int b   = qb >> 1;
            int cc  = qb & 1;
            so = (row * 10 + col) * 36 + b * 2 + cc;
            int ih = oh - 1 + row;
            int iw = ow0 - 1 + col;
            if ((unsigned)ih < 64u && (unsigned)iw < 64u)
                xgofs[s] = (b * 32 + cc) * 4096 + ih * 64 + iw;
        }
        if (s & 1) xpack[s >> 1] |= (unsigned)so << 16;
        else       xpack[s >> 1]  = (unsigned)so;
    }
    const bool has7 = (tid < 64);

    const int wreadb = pix * 576;                 // (pix*9) * 64
    const int xreadb = pix * 36 + bg * 8;

    u64t acc[4][8];
#pragma unroll
    for (int i = 0; i < 4; ++i)
#pragma unroll
        for (int j = 0; j < 8; ++j) acc[i][j] = 0ull;

    // fused load->stage for c-pair CC2 into buffer BUF; regs transient only
#define LOADSTAGE(CC2, BUF)                                                   \
    do {                                                                      \
        int cl = (CC2) << 1;                                                  \
        float4 wreg[9];                                                       \
        float  xreg[8];                                                       \
        _Pragma("unroll")                                                     \
        for (int s = 0; s < 9; ++s)                                           \
            wreg[s] = *reinterpret_cast<const float4*>(                       \
                wgt + wgofs[s] + cl * 36864);                                 \
        _Pragma("unroll")                                                     \
        for (int s = 0; s < 7; ++s)                                           \
            xreg[s] = (xgofs[s] >= 0) ? __ldg(xin + xgofs[s] + cl * 4096)     \
                                      : 0.f;                                  \
        if (has7)                                                             \
            xreg[7] = (xgofs[7] >= 0) ? __ldg(xin + xgofs[7] + cl * 4096)     \
                                      : 0.f;                                  \
        float* wd = sh + (BUF) * WBUF_F;                                      \
        float* xd = sh + XBASE_F + (BUF) * XBUF_F;                            \
        _Pragma("unroll")                                                     \
        for (int s = 0; s < 9; ++s) {                                         \
            wd[wpack[2*s] & 0xffffu]   = wreg[s].x;                           \
            wd[wpack[2*s] >> 16]       = wreg[s].y;                           \
            wd[wpack[2*s+1] & 0xffffu] = wreg[s].z;                           \
            wd[wpack[2*s+1] >> 16]     = wreg[s].w;                           \
        }                                                                     \
        _Pragma("unroll")                                                     \
        for (int s = 0; s < 7; ++s)                                           \
            xd[(xpack[s>>1] >> ((s&1)*16)) & 0xffffu] = xreg[s];              \
        if (has7) xd[xpack[3] >> 16] = xreg[7];                               \
    } while (0)

    // registerless L2 prefetch of iteration CC2's weight lines
#define PREFETCH(CC2)                                                         \
    do {                                                                      \
        int cl = (CC2) << 1;                                                  \
        _Pragma("unroll")                                                     \
        for (int s = 0; s < 9; ++s)                                           \
            asm volatile("prefetch.global.L2 [%0];" ::                        \
                         "l"(wgt + wgofs[s] + cl * 36864));                   \
    } while (0)

    // prologue: fill buf0; warm L2 for cc2=1
    LOADSTAGE(0, 0);
    PREFETCH(1);

    for (int cc2 = 0; cc2 < 16; ++cc2) {
        const int buf = cc2 & 1;
        __syncthreads();                    // buf staged; buf^1 fully consumed
        if (cc2 < 15) LOADSTAGE(cc2 + 1, buf ^ 1);
        if (cc2 < 14) PREFETCH(cc2 + 2);

        const float* wp = sh + buf * WBUF_F + wreadb;
        const float* xp = sh + XBASE_F + buf * XBUF_F + xreadb;
#pragma unroll
        for (int k = 0; k < 9; ++k) {
            const int f0k = (k < 8) ? k : 3;
            const float* xb = xp + ((k / 3) * 10 + (k % 3)) * 36;
            ulonglong2 xlo = *reinterpret_cast<const ulonglong2*>(xb);
            ulonglong2 xhi = *reinterpret_cast<const ulonglong2*>(xb + 4);
            u64t xv[4] = {xlo.x, xlo.y, xhi.x, xhi.y};

            const float* wb = wp + k * 64;
            const int t = og + ((f0k + 4 * pix) & 7);
            {   // o half 0: oi 0..3
                ulonglong2 wa = *reinterpret_cast<const ulonglong2*>(wb + ((t    ) & 15) * 4);
                ulonglong2 wc = *reinterpret_cast<const ulonglong2*>(wb + ((t + 4) & 15) * 4);
                u64t wv[4] = {wa.x, wa.y, wc.x, wc.y};
#pragma unroll
                for (int bi = 0; bi < 4; ++bi)
#pragma unroll
                    for (int oi = 0; oi < 4; ++oi)
                        acc[bi][oi] = fma_f32x2(xv[bi], wv[oi], acc[bi][oi]);
            }
            {   // o half 1: oi 4..7
                ulonglong2 wa = *reinterpret_cast<const ulonglong2*>(wb + ((t +  8) & 15) * 4);
                ulonglong2 wc = *reinterpret_cast<const ulonglong2*>(wb + ((t + 12) & 15) * 4);
                u64t wv[4] = {wa.x, wa.y, wc.x, wc.y};
#pragma unroll
                for (int bi = 0; bi < 4; ++bi)
#pragma unroll
                    for (int oi = 0; oi < 4; ++oi)
                        acc[bi][oi + 4] = fma_f32x2(xv[bi], wv[oi], acc[bi][oi + 4]);
            }
        }
    }

    // epilogue: sum cc pair, undo rotation swap, transpose via smem, 32B STG
    __syncthreads();
#pragma unroll
    for (int bi = 0; bi < 4; ++bi)
#pragma unroll
        for (int oi = 0; oi < 8; ++oi) {
            union { u64t u; float2 f; } cv;
            cv.u = acc[bi][oi];
            int bo = (bg * 4 + bi) * 32 + og * 8 + (oi ^ swp);
            sh[bo * 10 + pix] = cv.f.x + cv.f.y;
        }
    __syncthreads();
#pragma unroll
    for (int rr = 0; rr < 4; ++rr) {
        int r = tid + rr * 128;             // r = b*32 + o
        const float* sp = sh + r * 10;
        float4 lo = make_float4(sp[0], sp[1], sp[2], sp[3]);
        float4 hi = make_float4(sp[4], sp[5], sp[6], sp[7]);
        float* op = out + (size_t)r * 4096 + pixbase;
        *reinterpret_cast<float4*>(op)     = lo;
        *reinterpret_cast<float4*>(op + 4) = hi;
    }
#undef LOADSTAGE
#undef PREFETCH
}

extern "C" void kernel_launch(void* const* d_in, const int* in_sizes, int n_in,
                              void* d_out, int out_size) {
    const float* x = (const float*)d_in[0];   // [16,32,64,64] float32
    const float* w = (const float*)d_in[1];   // [32,32,64,64,9] float32
    float* y = (float*)d_out;                 // [16,32,64,64] float32
    dim3 grid(8, 64);
    lc2d_main<<<grid, 128>>>(x, w, y);
}

// round 11
// speedup vs baseline: 1.2379x; 1.2379x over previous
// LocallyConnected2d (B=16, C=32, O=32, 64x64, k=3x3, pad=1) — sm_100a.
// Block = 8 adjacent pixels, 128 threads; warp = 2 pixels; thread tile
// 4b x 8o, fp32x2 over channel pairs. Weight smem: row pk = 64 floats,
// chunk j of o-slot og at granule (4j+og+r(pk)) mod 16,
// r(pk) = (F0(pk%9)+4*(pk/9)) mod 8, F0={0,1,2,3,4,5,6,7,3}; intra-granule
// rotate 2*((pk/9)&1). Compute LDS.128 = 1 wavefront; staging STS <= 2-way.
// R11: R9 distance-2 REGISTER prefetch kept; index pressure cut via
// affine gmem assignment (run=tid>>1, v4=par+2s -> addr = wb + 8s) and
// 6-bit packed STS offsets; split-oi compute halves. launch_bounds(128,2).

#include <cuda_runtime.h>

typedef unsigned long long u64t;

__device__ __forceinline__ u64t fma_f32x2(u64t a, u64t b, u64t c) {
    u64t d;
    asm("fma.rn.f32x2 %0, %1, %2, %3;" : "=l"(d) : "l"(a), "l"(b), "l"(c));
    return d;
}

#define WBUF_F 4608
#define XBUF_F 1080
#define XBASE_F (2 * WBUF_F)

__global__ __launch_bounds__(128, 2)
void lc2d_main(const float* __restrict__ xin,
               const float* __restrict__ wgt,
               float* __restrict__ out)
{
    __shared__ __align__(16) float sh[2 * WBUF_F + 2 * XBUF_F];  // 45.5 KB

    const int tid  = threadIdx.x;
    const int lane = tid & 31;
    const int og   = lane & 3;
    const int bg   = (lane >> 2) & 3;
    const int pix  = (tid >> 5) * 2 + (lane >> 4);   // 0..7
    const int swp  = pix & 1;

    const int oh      = blockIdx.y;
    const int ow0     = blockIdx.x << 3;
    const int pixbase = oh * 64 + ow0;

    // ---- w staging invariants (affine): run = tid>>1, v4 = par + 2s ----
    const int par = tid & 1;
    const int wo  = tid >> 2;              // o of this thread's run
    const int wcc = (tid >> 1) & 1;        // cc of this thread's run
    const int wb  = ((wo * 32 + wcc) * 4096 + pixbase) * 9 + 4 * par;
    const int pb  = 256 * par;             // (4*par)*64

    unsigned lowp[9];                      // 4 x 6-bit lowparts per s
    {
        int idx16 = (wo & 7) * 2 + wcc;
        int Cb    = (idx16 & ~3) + (wo >> 3);
        int pos0  = idx16 & 3;
#pragma unroll
        for (int s = 0; s < 9; ++s) {
            unsigned v = 0;
#pragma unroll
            for (int e = 0; e < 4; ++e) {
                int pk = 4 * par + 8 * s + e;        // 0..71
                int p  = (pk * 57) >> 9;             // == pk / 9
                int q  = pk - p * 9;
                int f0 = q - 5 * (q >> 3);           // {0..7,3}
                int rt = (f0 + 4 * p) & 7;
                unsigned low = ((Cb + rt) & 15) * 4 +
                               ((pos0 + 2 * (p & 1)) & 3);
                v |= low << (6 * e);
            }
            lowp[s] = v;
        }
    }

    // ---- x staging invariants: slots 0..6 all threads, slot 7 iff tid<64 ----
    int xgofs[8];
    unsigned xpack[4];
#pragma unroll
    for (int s = 0; s < 8; ++s) {
        int i  = tid + s * 128;
        int so = 0;
        xgofs[s] = -1;
        if (i < 960) {
            int col = i % 10;
            int r   = i / 10;
            int row = r % 3;
            int qb  = r / 3;
            int b   = qb >> 1;
            int cc  = qb & 1;
            so = (row * 10 + col) * 36 + b * 2 + cc;
            int ih = oh - 1 + row;
            int iw = ow0 - 1 + col;
            if ((unsigned)ih < 64u && (unsigned)iw < 64u)
                xgofs[s] = (b * 32 + cc) * 4096 + ih * 64 + iw;
        }
        if (s & 1) xpack[s >> 1] |= (unsigned)so << 16;
        else       xpack[s >> 1]  = (unsigned)so;
    }
    const bool has7 = (tid < 64);

    const int wreadb = pix * 576;                 // (pix*9) * 64
    const int xreadb = pix * 36 + bg * 8;

    u64t acc[4][8];
#pragma unroll
    for (int i = 0; i < 4; ++i)
#pragma unroll
        for (int j = 0; j < 8; ++j) acc[i][j] = 0ull;

    float4 wreg[9];
    float  xreg[8];

#define DO_LOADS(CC2)                                                         \
    do {                                                                      \
        int cl = (CC2) << 1;                                                  \
        _Pragma("unroll")                                                     \
        for (int s = 0; s < 9; ++s)                                           \
            wreg[s] = *reinterpret_cast<const float4*>(                       \
                wgt + wb + cl * 36864 + s * 8);                               \
        _Pragma("unroll")                                                     \
        for (int s = 0; s < 7; ++s)                                           \
            xreg[s] = (xgofs[s] >= 0) ? __ldg(xin + xgofs[s] + cl * 4096)     \
                                      : 0.f;                                  \
        if (has7)                                                             \
            xreg[7] = (xgofs[7] >= 0) ? __ldg(xin + xgofs[7] + cl * 4096)     \
                                      : 0.f;                                  \
    } while (0)

#define DO_STAGE(BUF)                                                         \
    do {                                                                      \
        float* wd = sh + (BUF) * WBUF_F + pb;                                 \
        float* xd = sh + XBASE_F + (BUF) * XBUF_F;                            \
        _Pragma("unroll")                                                     \
        for (int s = 0; s < 9; ++s) {                                         \
            wd[s * 512 +       (lowp[s]        & 63u)] = wreg[s].x;           \
            wd[s * 512 +  64 + ((lowp[s] >>  6) & 63u)] = wreg[s].y;          \
            wd[s * 512 + 128 + ((lowp[s] >> 12) & 63u)] = wreg[s].z;          \
            wd[s * 512 + 192 + ((lowp[s] >> 18) & 63u)] = wreg[s].w;          \
        }                                                                     \
        _Pragma("unroll")                                                     \
        for (int s = 0; s < 7; ++s)                                           \
            xd[(xpack[s>>1] >> ((s&1)*16)) & 0xffffu] = xreg[s];              \
        if (has7) xd[xpack[3] >> 16] = xreg[7];                               \
    } while (0)

    DO_LOADS(0);
    DO_STAGE(0);
    DO_LOADS(1);

    for (int cc2 = 0; cc2 < 16; ++cc2) {
        const int buf = cc2 & 1;
        __syncthreads();                    // buf staged; buf^1 fully consumed
        if (cc2 < 15) DO_STAGE(buf ^ 1);
        if (cc2 < 14) DO_LOADS(cc2 + 2);

        const float* wp = sh + buf * WBUF_F + wreadb;
        const float* xp = sh + XBASE_F + buf * XBUF_F + xreadb;
#pragma unroll
        for (int k = 0; k < 9; ++k) {
            const int f0k = (k < 8) ? k : 3;
            const float* xb = xp + ((k / 3) * 10 + (k % 3)) * 36;
            ulonglong2 xlo = *reinterpret_cast<const ulonglong2*>(xb);
            ulonglong2 xhi = *reinterpret_cast<const ulonglong2*>(xb + 4);
            u64t xv[4] = {xlo.x, xlo.y, xhi.x, xhi.y};

            const float* wkb = wp + k * 64;
            const int t = og + ((f0k + 4 * pix) & 7);
            {   // o half 0: oi 0..3
                ulonglong2 wa = *reinterpret_cast<const ulonglong2*>(wkb + ((t    ) & 15) * 4);
                ulonglong2 wc = *reinterpret_cast<const ulonglong2*>(wkb + ((t + 4) & 15) * 4);
                u64t wv[4] = {wa.x, wa.y, wc.x, wc.y};
#pragma unroll
                for (int bi = 0; bi < 4; ++bi)
#pragma unroll
                    for (int oi = 0; oi < 4; ++oi)
                        acc[bi][oi] = fma_f32x2(xv[bi], wv[oi], acc[bi][oi]);
            }
            {   // o half 1: oi 4..7
                ulonglong2 wa = *reinterpret_cast<const ulonglong2*>(wkb + ((t +  8) & 15) * 4);
                ulonglong2 wc = *reinterpret_cast<const ulonglong2*>(wkb + ((t + 12) & 15) * 4);
                u64t wv[4] = {wa.x, wa.y, wc.x, wc.y};
#pragma unroll
                for (int bi = 0; bi < 4; ++bi)
#pragma unroll
                    for (int oi = 0; oi < 4; ++oi)
                        acc[bi][oi + 4] = fma_f32x2(xv[bi], wv[oi], acc[bi][oi + 4]);
            }
        }
    }

    // epilogue: sum cc pair, undo rotation swap, transpose via smem, 32B STG
    __syncthreads();
#pragma unroll
    for (int bi = 0; bi < 4; ++bi)
#pragma unroll
        for (int oi = 0; oi < 8; ++oi) {
            union { u64t u; float2 f; } cv;
            cv.u = acc[bi][oi];
            int bo = (bg * 4 + bi) * 32 + og * 8 + (oi ^ swp);
            sh[bo * 10 + pix] = cv.f.x + cv.f.y;
        }
    __syncthreads();
#pragma unroll
    for (int rr = 0; rr < 4; ++rr) {
        int r = tid + rr * 128;             // r = b*32 + o
        const float* sp = sh + r * 10;
        float4 lo = make_float4(sp[0], sp[1], sp[2], sp[3]);
        float4 hi = make_float4(sp[4], sp[5], sp[6], sp[7]);
        float* op = out + (size_t)r * 4096 + pixbase;
        *reinterpret_cast<float4*>(op)     = lo;
        *reinterpret_cast<float4*>(op + 4) = hi;
    }
#undef DO_LOADS
#undef DO_STAGE
}

extern "C" void kernel_launch(void* const* d_in, const int* in_sizes, int n_in,
                              void* d_out, int out_size) {
    const float* x = (const float*)d_in[0];   // [16,32,64,64] float32
    const float* w = (const float*)d_in[1];   // [32,32,64,64,9] float32
    float* y = (float*)d_out;                 // [16,32,64,64] float32
    dim3 grid(8, 64);
    lc2d_main<<<grid, 128>>>(x, w, y);
}

// round 12
// speedup vs baseline: 1.5374x; 1.2420x over previous
// LocallyConnected2d (B=16, C=32, O=32, 64x64, k=3x3, pad=1) — sm_100a.
// Block = 8 adjacent pixels, 128 threads; warp = 2 pixels; thread tile
// 4b x 8o, fp32x2 over channel pairs. Weight smem: row pk = 64 floats,
// chunk j of o-slot og at granule (4j+og+r(pk)) mod 16,
// r(pk) = (F0(pk%9)+4*(pk/9)) mod 8, F0={0,1,2,3,4,5,6,7,3}; intra-granule
// rotate 2*((pk/9)&1). Compute LDS.128 = 1 wavefront; STS <= ~2-way.
// R12 (base = R9, the 69.6us best): w staging vectorized as cc-pair STS.64
// (16 x st.shared.v2.b32 + 4 x STS.32 leftover), R9-style contiguous LDG
// lane assignment kept, distance-2 register prefetch kept, split-oi compute.

#include <cuda_runtime.h>

typedef unsigned long long u64t;

__device__ __forceinline__ u64t fma_f32x2(u64t a, u64t b, u64t c) {
    u64t d;
    asm("fma.rn.f32x2 %0, %1, %2, %3;" : "=l"(d) : "l"(a), "l"(b), "l"(c));
    return d;
}

#define WBUF_F 4608
#define XBUF_F 1080
#define XBASE_F (2 * WBUF_F)
#define CC_STRIDE 36864                    // c stride in w (floats)

// smem float offset for weight element (pk, o, cc)
__device__ __forceinline__ int w_smem_off(int pk, int o, int cc) {
    int idx16 = (o & 7) * 2 + cc;
    int Cb    = (idx16 & ~3) + (o >> 3);
    int pos0  = idx16 & 3;
    int p  = (pk * 57) >> 9;               // == pk / 9 for pk < 72
    int q  = pk - p * 9;
    int f0 = q - 5 * (q >> 3);             // {0,1,2,3,4,5,6,7,3}
    int rt = (f0 + 4 * p) & 7;
    return pk * 64 + ((Cb + rt) & 15) * 4 + ((pos0 + 2 * (p & 1)) & 3);
}

__global__ __launch_bounds__(128, 2)
void lc2d_main(const float* __restrict__ xin,
               const float* __restrict__ wgt,
               float* __restrict__ out)
{
    __shared__ __align__(16) float sh[2 * WBUF_F + 2 * XBUF_F];  // 45.5 KB

    const int tid  = threadIdx.x;
    const int lane = tid & 31;
    const int og   = lane & 3;
    const int bg   = (lane >> 2) & 3;
    const int pix  = (tid >> 5) * 2 + (lane >> 4);   // 0..7
    const int swp  = pix & 1;

    const int oh      = blockIdx.y;
    const int ow0     = blockIdx.x << 3;
    const int pixbase = oh * 64 + ow0;

    // ---- w staging: 4 cc-pair items (o = idx>>4, v4 = idx&15, idx=j*128+tid)
    //      + 1 leftover quad (v4 in {16,17}) ----
    int  wpb[4];                 // gmem float base of cc=0 quad per item
    unsigned p64[8];             // 4 items x 4 STS.64 offsets, packed 16-bit
#pragma unroll
    for (int j = 0; j < 4; ++j) {
        int idx = j * 128 + tid;
        int o   = idx >> 4;
        int v4  = idx & 15;
        wpb[j]  = o * (32 * CC_STRIDE) + pixbase * 9 + v4 * 4;
        unsigned a = 0, b = 0;
#pragma unroll
        for (int e = 0; e < 4; ++e) {
            int off = w_smem_off(v4 * 4 + e, o, 0);   // cc=1 is off+1
            if (e < 2) a |= (unsigned)off << (16 * e);
            else       b |= (unsigned)off << (16 * (e - 2));
        }
        p64[j * 2] = a; p64[j * 2 + 1] = b;
    }
    int wlb;                     // leftover quad gmem base
    unsigned pL[2];              // 4 STS.32 offsets packed 16-bit
    {
        int o  = tid >> 2;
        int t2 = tid & 3;
        int cc = t2 & 1;
        int v4 = 16 + (t2 >> 1);
        wlb = (o * 32 + cc) * CC_STRIDE + pixbase * 9 + v4 * 4;
        unsigned a = 0, b = 0;
#pragma unroll
        for (int e = 0; e < 4; ++e) {
            int off = w_smem_off(v4 * 4 + e, o, cc);
            if (e < 2) a |= (unsigned)off << (16 * e);
            else       b |= (unsigned)off << (16 * (e - 2));
        }
        pL[0] = a; pL[1] = b;
    }

    // ---- x staging invariants: slots 0..6 all threads, slot 7 iff tid<64 ----
    int xgofs[8];
    unsigned xpack[4];
#pragma unroll
    for (int s = 0; s < 8; ++s) {
        int i  = tid + s * 128;
        int so = 0;
        xgofs[s] = -1;
        if (i < 960) {
            int col = i % 10;
            int r   = i / 10;
            int row = r % 3;
            int qb  = r / 3;
            int b   = qb >> 1;
            int cc  = qb & 1;
            so = (row * 10 + col) * 36 + b * 2 + cc;
            int ih = oh - 1 + row;
            int iw = ow0 - 1 + col;
            if ((unsigned)ih < 64u && (unsigned)iw < 64u)
                xgofs[s] = (b * 32 + cc) * 4096 + ih * 64 + iw;
        }
        if (s & 1) xpack[s >> 1] |= (unsigned)so << 16;
        else       xpack[s >> 1]  = (unsigned)so;
    }
    const bool has7 = (tid < 64);

    const int wreadb = pix * 576;                 // (pix*9) * 64
    const int xreadb = pix * 36 + bg * 8;

    u64t acc[4][8];
#pragma unroll
    for (int i = 0; i < 4; ++i)
#pragma unroll
        for (int j = 0; j < 8; ++j) acc[i][j] = 0ull;

    float4 wA[4], wB[4], wL;
    float  xreg[8];

#define DO_LOADS(CC2)                                                         \
    do {                                                                      \
        int cl = (CC2) * (2 * CC_STRIDE);                                     \
        _Pragma("unroll")                                                     \
        for (int j = 0; j < 4; ++j) {                                         \
            wA[j] = *reinterpret_cast<const float4*>(wgt + wpb[j] + cl);      \
            wB[j] = *reinterpret_cast<const float4*>(wgt + wpb[j] + cl        \
                                                     + CC_STRIDE);            \
        }                                                                     \
        wL = *reinterpret_cast<const float4*>(wgt + wlb + cl);                \
        int cx = (CC2) * 8192;                                                \
        _Pragma("unroll")                                                     \
        for (int s = 0; s < 7; ++s)                                           \
            xreg[s] = (xgofs[s] >= 0) ? __ldg(xin + xgofs[s] + cx) : 0.f;     \
        if (has7)                                                             \
            xreg[7] = (xgofs[7] >= 0) ? __ldg(xin + xgofs[7] + cx) : 0.f;     \
    } while (0)

#define DO_STAGE(BUF)                                                         \
    do {                                                                      \
        float* wd = sh + (BUF) * WBUF_F;                                      \
        float* xd = sh + XBASE_F + (BUF) * XBUF_F;                            \
        _Pragma("unroll")                                                     \
        for (int j = 0; j < 4; ++j) {                                         \
            const float* a = reinterpret_cast<const float*>(&wA[j]);          \
            const float* b = reinterpret_cast<const float*>(&wB[j]);          \
            _Pragma("unroll")                                                 \
            for (int e = 0; e < 4; ++e) {                                     \
                unsigned off = (p64[j*2 + (e>>1)] >> (16*(e&1))) & 0xffffu;   \
                *reinterpret_cast<float2*>(wd + off) =                        \
                    make_float2(a[e], b[e]);                                  \
            }                                                                 \
        }                                                                     \
        {                                                                     \
            const float* l = reinterpret_cast<const float*>(&wL);             \
            wd[pL[0] & 0xffffu] = l[0];                                       \
            wd[pL[0] >> 16]     = l[1];                                       \
            wd[pL[1] & 0xffffu] = l[2];                                       \
            wd[pL[1] >> 16]     = l[3];                                       \
        }                                                                     \
        _Pragma("unroll")                                                     \
        for (int s = 0; s < 7; ++s)                                           \
            xd[(xpack[s>>1] >> ((s&1)*16)) & 0xffffu] = xreg[s];              \
        if (has7) xd[xpack[3] >> 16] = xreg[7];                               \
    } while (0)

    DO_LOADS(0);
    DO_STAGE(0);
    DO_LOADS(1);

    for (int cc2 = 0; cc2 < 16; ++cc2) {
        const int buf = cc2 & 1;
        __syncthreads();                    // buf staged; buf^1 fully consumed
        if (cc2 < 15) DO_STAGE(buf ^ 1);
        if (cc2 < 14) DO_LOADS(cc2 + 2);

        const float* wp = sh + buf * WBUF_F + wreadb;
        const float* xp = sh + XBASE_F + buf * XBUF_F + xreadb;
#pragma unroll
        for (int k = 0; k < 9; ++k) {
            const int f0k = (k < 8) ? k : 3;
            const float* xb = xp + ((k / 3) * 10 + (k % 3)) * 36;
            ulonglong2 xlo = *reinterpret_cast<const ulonglong2*>(xb);
            ulonglong2 xhi = *reinterpret_cast<const ulonglong2*>(xb + 4);
            u64t xv[4] = {xlo.x, xlo.y, xhi.x, xhi.y};

            const float* wkb = wp + k * 64;
            const int t = og + ((f0k + 4 * pix) & 7);
            {   // o half 0: oi 0..3
                ulonglong2 wa = *reinterpret_cast<const ulonglong2*>(wkb + ((t    ) & 15) * 4);
                ulonglong2 wc = *reinterpret_cast<const ulonglong2*>(wkb + ((t + 4) & 15) * 4);
                u64t wv[4] = {wa.x, wa.y, wc.x, wc.y};
#pragma unroll
                for (int bi = 0; bi < 4; ++bi)
#pragma unroll
                    for (int oi = 0; oi < 4; ++oi)
                        acc[bi][oi] = fma_f32x2(xv[bi], wv[oi], acc[bi][oi]);
            }
            {   // o half 1: oi 4..7
                ulonglong2 wa = *reinterpret_cast<const ulonglong2*>(wkb + ((t +  8) & 15) * 4);
                ulonglong2 wc = *reinterpret_cast<const ulonglong2*>(wkb + ((t + 12) & 15) * 4);
                u64t wv[4] = {wa.x, wa.y, wc.x, wc.y};
#pragma unroll
                for (int bi = 0; bi < 4; ++bi)
#pragma unroll
                    for (int oi = 0; oi < 4; ++oi)
                        acc[bi][oi + 4] = fma_f32x2(xv[bi], wv[oi], acc[bi][oi + 4]);
            }
        }
    }

    // epilogue: sum cc pair, undo rotation swap, transpose via smem, 32B STG
    __syncthreads();
#pragma unroll
    for (int bi = 0; bi < 4; ++bi)
#pragma unroll
        for (int oi = 0; oi < 8; ++oi) {
            union { u64t u; float2 f; } cv;
            cv.u = acc[bi][oi];
            int bo = (bg * 4 + bi) * 32 + og * 8 + (oi ^ swp);
            sh[bo * 10 + pix] = cv.f.x + cv.f.y;
        }
    __syncthreads();
#pragma unroll
    for (int rr = 0; rr < 4; ++rr) {
        int r = tid + rr * 128;             // r = b*32 + o
        const float* sp = sh + r * 10;
        float4 lo = make_float4(sp[0], sp[1], sp[2], sp[3]);
        float4 hi = make_float4(sp[4], sp[5], sp[6], sp[7]);
        float* op = out + (size_t)r * 4096 + pixbase;
        *reinterpret_cast<float4*>(op)     = lo;
        *reinterpret_cast<float4*>(op + 4) = hi;
    }
#undef DO_LOADS
#undef DO_STAGE
}

extern "C" void kernel_launch(void* const* d_in, const int* in_sizes, int n_in,
                              void* d_out, int out_size) {
    const float* x = (const float*)d_in[0];   // [16,32,64,64] float32
    const float* w = (const float*)d_in[1];   // [32,32,64,64,9] float32
    float* y = (float*)d_out;                 // [16,32,64,64] float32
    dim3 grid(8, 64);
    lc2d_main<<<grid, 128>>>(x, w, y);
}